// round 13
// baseline (speedup 1.0000x reference)
#include <cuda_runtime.h>

// Problem constants (fixed by the reference: mulElements hard-codes 8000 rows)
#define NN 8000
#define DD 9
#define NJ4 (NN / 4)            // 2000 float4 per output row
#define ROWS_PER_BLOCK 32
#define PT 512                  // prologue threads
#define RPT 16                  // rows per prologue thread (500 live threads)

// Scratch (allocation-free rule: __device__ globals). 16B-aligned for float4 IO.
__device__ __align__(16) float g_f1[NN];   // x @ w_fc1.T + b_fc1
__device__ __align__(16) float g_f2[NN];
__device__ __align__(16) float g_w1b[NN];  // normalized cumulative weights
__device__ __align__(16) float g_w2b[NN];

// ---------------------------------------------------------------------------
// Fused prologue, ONE block of 512 threads, zero global round-trips.
// Thread t (t<500) owns rows [16t, 16t+16): floats [144t, 144t+144) of x,
// i.e. 36 aligned float4 loads in 4 batches of 9 (4 rows per batch — 4*9=36
// floats tiles exactly into 9 float4s). Per row: quadratic sums z1,z2 and the
// two 9->1 dot products. z stays in registers: local inclusive cumsum, then
// one block scan of thread totals, then w = exp(-prefix) normalized.
// cumprod(prod(exp(-z))) == exp(-cumsum(sum(z))).
// ---------------------------------------------------------------------------
__global__ __launch_bounds__(PT) void prologue_kernel(
        const float* __restrict__ x,
        const float* __restrict__ a1,
        const float* __restrict__ c1,
        const float* __restrict__ a2,
        const float* __restrict__ c2,
        const float* __restrict__ wfc1,
        const float* __restrict__ bfc1,
        const float* __restrict__ wfc2,
        const float* __restrict__ bfc2) {
    const int tid = threadIdx.x;
    const int lane = tid & 31;
    const int wid = tid >> 5;
    const bool live = (tid < NN / RPT);    // 500 live threads

    float cum1[RPT], cum2[RPT];            // in-thread inclusive cumsum of z
    float ta = 0.0f, tb = 0.0f;            // thread totals

    if (live) {
        const float ia1 = 1.0f / a1[0];
        const float ia2 = 1.0f / a2[0];
        const float cc1 = c1[0];
        const float cc2 = c2[0];
        const float b1 = bfc1[0];
        const float b2 = bfc2[0];
        float wf1[DD], wf2[DD];
#pragma unroll
        for (int j = 0; j < DD; j++) { wf1[j] = wfc1[j]; wf2[j] = wfc2[j]; }

        const float4* xb = reinterpret_cast<const float4*>(x) + tid * 36;
        float run1 = 0.0f, run2 = 0.0f;
        float fo1[RPT], fo2[RPT];

#pragma unroll
        for (int b = 0; b < 4; b++) {      // 4 batches of 4 rows
            float4 q[9];
#pragma unroll
            for (int k = 0; k < 9; k++) q[k] = xb[b * 9 + k];
            float v[36];
#pragma unroll
            for (int k = 0; k < 9; k++) {
                v[4 * k + 0] = q[k].x; v[4 * k + 1] = q[k].y;
                v[4 * k + 2] = q[k].z; v[4 * k + 3] = q[k].w;
            }
#pragma unroll
            for (int r = 0; r < 4; r++) {  // rows within batch
                const int row = b * 4 + r;
                float z1 = 0.0f, z2 = 0.0f;
                float f1 = b1, f2 = b2;
#pragma unroll
                for (int j = 0; j < DD; j++) {
                    float val = v[r * DD + j];
                    float t1 = (val - cc1) * ia1;
                    float t2 = (val - cc2) * ia2;
                    z1 = fmaf(t1, t1, z1);
                    z2 = fmaf(t2, t2, z2);
                    f1 = fmaf(val, wf1[j], f1);
                    f2 = fmaf(val, wf2[j], f2);
                }
                run1 += z1; run2 += z2;
                cum1[row] = run1; cum2[row] = run2;
                fo1[row] = f1;   fo2[row] = f2;
            }
        }
        ta = run1; tb = run2;

        // store f as 4 float4 per array
        float4* f1v = reinterpret_cast<float4*>(g_f1);
        float4* f2v = reinterpret_cast<float4*>(g_f2);
#pragma unroll
        for (int g = 0; g < 4; g++) {
            f1v[4 * tid + g] = make_float4(fo1[4 * g], fo1[4 * g + 1],
                                           fo1[4 * g + 2], fo1[4 * g + 3]);
            f2v[4 * tid + g] = make_float4(fo2[4 * g], fo2[4 * g + 1],
                                           fo2[4 * g + 2], fo2[4 * g + 3]);
        }
    }

    // ---- block scan of thread totals (16 warps) ----
    __shared__ float2 s_warp[16];
    float sa = ta, sb = tb;
#pragma unroll
    for (int off = 1; off < 32; off <<= 1) {
        float xa = __shfl_up_sync(0xffffffffu, sa, off);
        float xb2 = __shfl_up_sync(0xffffffffu, sb, off);
        if (lane >= off) { sa += xa; sb += xb2; }
    }
    if (lane == 31) s_warp[wid] = make_float2(sa, sb);
    __syncthreads();

    if (wid == 0) {
        float wa = (lane < 16) ? s_warp[lane].x : 0.0f;
        float wb = (lane < 16) ? s_warp[lane].y : 0.0f;
#pragma unroll
        for (int off = 1; off < 32; off <<= 1) {
            float xa = __shfl_up_sync(0xffffffffu, wa, off);
            float xb2 = __shfl_up_sync(0xffffffffu, wb, off);
            if (lane >= off) { wa += xa; wb += xb2; }
        }
        if (lane < 16) s_warp[lane] = make_float2(wa, wb);
    }
    __syncthreads();

    float offa = sa - ta;                  // exclusive within warp
    float offb = sb - tb;
    if (wid > 0) { offa += s_warp[wid - 1].x; offb += s_warp[wid - 1].y; }

    if (live) {
        float4* w1v = reinterpret_cast<float4*>(g_w1b);
        float4* w2v = reinterpret_cast<float4*>(g_w2b);
#pragma unroll
        for (int g = 0; g < 4; g++) {
            float o1[4], o2[4];
#pragma unroll
            for (int r = 0; r < 4; r++) {
                const int row = 4 * g + r;
                float w1 = expf(-(offa + cum1[row]));
                float w2 = expf(-(offb + cum2[row]));
                float inv = 1.0f / (w1 + w2);
                o1[r] = w1 * inv;
                o2[r] = w2 * inv;
            }
            w1v[4 * tid + g] = make_float4(o1[0], o1[1], o1[2], o1[3]);
            w2v[4 * tid + g] = make_float4(o2[0], o2[1], o2[2], o2[3]);
        }
    }
}

// ---------------------------------------------------------------------------
// Outer product: out[i][j] = f1[i]*w1b[j] + f2[i]*w2b[j]. 256 MB of streaming
// stores — the DRAM-write roofline (measured 38.2us, 65% DRAM). __stcs since
// the output is never re-read; 32 rows/block reuse the w float4s in registers.
// BYTE-IDENTICAL to R9's outer kernel.
// ---------------------------------------------------------------------------
__global__ __launch_bounds__(256) void outer_kernel(float4* __restrict__ out) {
    int j4 = blockIdx.x * blockDim.x + threadIdx.x;
    if (j4 >= NJ4) return;

    const float4 w1 = reinterpret_cast<const float4*>(g_w1b)[j4];
    const float4 w2 = reinterpret_cast<const float4*>(g_w2b)[j4];

    const int i0 = blockIdx.y * ROWS_PER_BLOCK;
#pragma unroll
    for (int r = 0; r < ROWS_PER_BLOCK; r++) {
        const int i = i0 + r;
        const float f1 = __ldg(&g_f1[i]);
        const float f2 = __ldg(&g_f2[i]);
        float4 o;
        o.x = fmaf(f1, w1.x, f2 * w2.x);
        o.y = fmaf(f1, w1.y, f2 * w2.y);
        o.z = fmaf(f1, w1.z, f2 * w2.z);
        o.w = fmaf(f1, w1.w, f2 * w2.w);
        __stcs(&out[(size_t)i * NJ4 + j4], o);
    }
}

// ---------------------------------------------------------------------------
extern "C" void kernel_launch(void* const* d_in, const int* in_sizes, int n_in,
                              void* d_out, int out_size) {
    const float* x    = (const float*)d_in[0];
    const float* a1   = (const float*)d_in[1];
    const float* c1   = (const float*)d_in[2];
    const float* a2   = (const float*)d_in[3];
    const float* c2   = (const float*)d_in[4];
    const float* wfc1 = (const float*)d_in[5];
    const float* bfc1 = (const float*)d_in[6];
    const float* wfc2 = (const float*)d_in[7];
    const float* bfc2 = (const float*)d_in[8];
    float4* out = (float4*)d_out;

    prologue_kernel<<<1, PT>>>(x, a1, c1, a2, c2, wfc1, bfc1, wfc2, bfc2);
    dim3 grid((NJ4 + 255) / 256, NN / ROWS_PER_BLOCK);
    outer_kernel<<<grid, 256>>>(out);
}